// round 15
// baseline (speedup 1.0000x reference)
#include <cuda_runtime.h>
#include <cuda_fp16.h>
#include <mma.h>
#include <cstdint>
using namespace nvcuda;

#define NUM_PROTEINS 19000
#define NUM_DRUGS    1024
#define EMBED        256
#define E_SG         1500000
#define N_SG         800000
#define B_DD         4096
#define NBLK         149            // ceil(19000/128)

// ---------------- scratch (device globals; no allocation) ----------------
__device__ uint4 g_hwh4[NUM_PROTEINS * EMBED / 8];      // GEMM out fp16
__device__ uint4 g_h1h4[NUM_PROTEINS * EMBED / 8];      // h1 fp16
__device__ uint2 g_q8v [NUM_PROTEINS * EMBED / 8];      // hw quantized int8
__device__ uint2 g_h2q [NUM_PROTEINS * EMBED / 8];      // h2 quantized int8
__device__ float g_h2s [NUM_PROTEINS];                  // h2 row scales
__device__ float g_qs  [NUM_PROTEINS];                  // quant row scale (m/127)
__device__ uint4 g_W1h4[EMBED * EMBED / 8];
__device__ uint4 g_W2h4[EMBED * EMBED / 8];
__device__ int   g_degi[NUM_PROTEINS];
__device__ float g_dinv[NUM_PROTEINS];
__device__ int   g_rowstart[NUM_PROTEINS + 1];
__device__ int   g_cursor[NUM_PROTEINS];
__device__ int   g_esrc[E_SG];
__device__ int   g_bsum[NBLK];
__device__ int   g_boff[NBLK];
__device__ int   g_scancnt;
__device__ int   g_scanflag;
__device__ float g_demb[NUM_DRUGS * EMBED];

// half2 magic-bias int8 decode + fused multiply-accumulate (R13-proven).
__device__ __forceinline__ void fma8h(__half2* acc, unsigned wu, uint2 v) {
    __half2 w2 = *(__half2*)&wu;
    unsigned cbits = 0x64806480u;              // half2(1152, 1152)
    __half2 c2 = *(__half2*)&cbits;
    unsigned ux = v.x ^ 0x80808080u;
    unsigned uy = v.y ^ 0x80808080u;
    unsigned p0 = __byte_perm(ux, 0x64646464u, 0x4140);
    unsigned p1 = __byte_perm(ux, 0x64646464u, 0x4342);
    unsigned p2 = __byte_perm(uy, 0x64646464u, 0x4140);
    unsigned p3 = __byte_perm(uy, 0x64646464u, 0x4342);
    acc[0] = __hfma2(w2, __hsub2(*(__half2*)&p0, c2), acc[0]);
    acc[1] = __hfma2(w2, __hsub2(*(__half2*)&p1, c2), acc[1]);
    acc[2] = __hfma2(w2, __hsub2(*(__half2*)&p2, c2), acc[2]);
    acc[3] = __hfma2(w2, __hsub2(*(__half2*)&p3, c2), acc[3]);
}

// pack float weight into replicated half2 bits
__device__ __forceinline__ unsigned packw2(float w) {
    unsigned hb = (unsigned)__half_as_ushort(__float2half_rn(w));
    return hb | (hb << 16);
}

// ---------------- prep0: convert W1/W2 to fp16, zero counters ----------------
__global__ void k_prep0(const float* __restrict__ W1, const float* __restrict__ W2,
                        __half* __restrict__ W1h, __half* __restrict__ W2h) {
    int i = blockIdx.x * blockDim.x + threadIdx.x;
    const int n4 = EMBED * EMBED / 4;
    if (i < n4) {
        float4 v = ((const float4*)W1)[i];
        ((__half2*)W1h)[2 * i]     = __floats2half2_rn(v.x, v.y);
        ((__half2*)W1h)[2 * i + 1] = __floats2half2_rn(v.z, v.w);
    } else {
        int j = i - n4;
        float4 v = ((const float4*)W2)[j];
        ((__half2*)W2h)[2 * j]     = __floats2half2_rn(v.x, v.y);
        ((__half2*)W2h)[2 * j + 1] = __floats2half2_rn(v.z, v.w);
    }
    if (i < NUM_PROTEINS) g_degi[i] = 0;
    if (i == 0) { g_scancnt = 0; g_scanflag = 0; }
}

// ---------------- degree count (8 edges per thread, 2x int4 loads) ----------------
__global__ void k_count(const int* __restrict__ dstb) {
    int t = blockIdx.x * blockDim.x + threadIdx.x;
    int e8 = t * 8;
    if (e8 + 8 <= E_SG) {
        int4 a = *(const int4*)(dstb + e8);
        int4 b = *(const int4*)(dstb + e8 + 4);
        atomicAdd(&g_degi[a.x], 1); atomicAdd(&g_degi[a.y], 1);
        atomicAdd(&g_degi[a.z], 1); atomicAdd(&g_degi[a.w], 1);
        atomicAdd(&g_degi[b.x], 1); atomicAdd(&g_degi[b.y], 1);
        atomicAdd(&g_degi[b.z], 1); atomicAdd(&g_degi[b.w], 1);
    } else {
        for (int e = e8; e < E_SG; ++e) atomicAdd(&g_degi[dstb[e]], 1);
    }
}

// ---------------- fused scan: block sums + global scan + rowstart/cursor/dinv ----------------
__global__ void k_scanall() {
    __shared__ int wsum[4];
    __shared__ int islast;
    __shared__ int sboff;
    __shared__ int sbsum[NBLK];
    int t = threadIdx.x, b = blockIdx.x;
    int j = b * 128 + t;
    int d = (j < NUM_PROTEINS) ? g_degi[j] : 0;
    int lane = t & 31, w = t >> 5;
    int v = d;
#pragma unroll
    for (int off = 1; off < 32; off <<= 1) {
        int u = __shfl_up_sync(0xffffffffu, v, off);
        if (lane >= off) v += u;
    }
    if (lane == 31) wsum[w] = v;
    __syncthreads();
    if (w == 0 && lane < 4) {
        int x = wsum[lane];
#pragma unroll
        for (int off = 1; off < 4; off <<= 1) {
            int u = __shfl_up_sync(0xfu, x, off);
            if (lane >= off) x += u;
        }
        wsum[lane] = x;
    }
    __syncthreads();
    if (t == 0) {
        g_bsum[b] = wsum[3];
        __threadfence();
        int prev = atomicAdd(&g_scancnt, 1);
        islast = (prev == NBLK - 1) ? 1 : 0;
    }
    __syncthreads();
    if (islast) {
        for (int i = t; i < NBLK; i += 128) sbsum[i] = g_bsum[i];
        __syncthreads();
        if (t == 0) {
            int run = 0;
#pragma unroll 4
            for (int i = 0; i < NBLK; ++i) { int s = sbsum[i]; sbsum[i] = run; run += s; }
        }
        __syncthreads();
        for (int i = t; i < NBLK; i += 128) g_boff[i] = sbsum[i];
        __threadfence();
        __syncthreads();
        if (t == 0) atomicExch(&g_scanflag, 1);
    }
    if (t == 0) {
        while (atomicAdd(&g_scanflag, 0) == 0) { }
        sboff = atomicAdd(&g_boff[b], 0);
    }
    __syncthreads();
    int run = sboff + (v - d) + (w ? wsum[w - 1] : 0);
    if (j < NUM_PROTEINS) {
        g_rowstart[j] = run;
        g_cursor[j]   = run;
        g_dinv[j]     = rsqrtf((float)d + 1.0f);
    }
    if (j == 0) g_rowstart[NUM_PROTEINS] = E_SG;
}

// ---------------- CSR fill (1 edge per thread — R8-proven) ----------------
__global__ void k_fill(const int* __restrict__ ei) {
    int e = blockIdx.x * blockDim.x + threadIdx.x;
    if (e >= E_SG) return;
    int s = ei[e];
    int d = ei[E_SG + e];
    int pos = atomicAdd(&g_cursor[d], 1);
    g_esrc[pos] = s;
}

// ---------------- WMMA fp16 GEMM ----------------
template<int AHALF>
__global__ void k_gemm_w(const void* __restrict__ Ap, const __half* __restrict__ B,
                         __half* __restrict__ C, int M) {
    __shared__ __align__(16) __half As[128][40];
    __shared__ __align__(16) __half Bs[32][72];
    __shared__ __align__(16) float  Cs[128][64];
    int bm = blockIdx.x * 128, bn = blockIdx.y * 64;
    int tid = threadIdx.x;
    int warp = tid >> 5;
    int wm = warp & 3, wn = warp >> 2;
    wmma::fragment<wmma::accumulator, 16, 16, 16, float> c[2][2];
#pragma unroll
    for (int i = 0; i < 2; ++i)
#pragma unroll
        for (int j = 0; j < 2; ++j) wmma::fill_fragment(c[i][j], 0.f);

    for (int k0 = 0; k0 < 256; k0 += 32) {
        if (AHALF) {
            const __half* A = (const __half*)Ap;
#pragma unroll
            for (int l = 0; l < 2; ++l) {
                int idx = tid + l * 256;
                int r = idx >> 2, seg = (idx & 3) * 8;
                uint4 v = make_uint4(0, 0, 0, 0);
                int gr = bm + r;
                if (gr < M) v = *(const uint4*)(A + (size_t)gr * 256 + k0 + seg);
                *(uint4*)&As[r][seg] = v;
            }
        } else {
            const float* A = (const float*)Ap;
#pragma unroll
            for (int l = 0; l < 4; ++l) {
                int idx = tid + l * 256;
                int r = idx >> 3, c4 = (idx & 7) * 4;
                float4 v = make_float4(0.f, 0.f, 0.f, 0.f);
                int gr = bm + r;
                if (gr < M) v = *(const float4*)(A + (size_t)gr * 256 + k0 + c4);
                *(__half2*)&As[r][c4]     = __floats2half2_rn(v.x, v.y);
                *(__half2*)&As[r][c4 + 2] = __floats2half2_rn(v.z, v.w);
            }
        }
        {
            int r = tid >> 3, seg = (tid & 7) * 8;
            uint4 v = *(const uint4*)(B + (size_t)(k0 + r) * 256 + bn + seg);
            *(uint4*)&Bs[r][seg] = v;
        }
        __syncthreads();
#pragma unroll
        for (int kk = 0; kk < 32; kk += 16) {
            wmma::fragment<wmma::matrix_a, 16, 16, 16, __half, wmma::row_major> a0, a1;
            wmma::fragment<wmma::matrix_b, 16, 16, 16, __half, wmma::row_major> b0, b1;
            wmma::load_matrix_sync(a0, &As[wm * 32][kk], 40);
            wmma::load_matrix_sync(a1, &As[wm * 32 + 16][kk], 40);
            wmma::load_matrix_sync(b0, &Bs[kk][wn * 32], 72);
            wmma::load_matrix_sync(b1, &Bs[kk][wn * 32 + 16], 72);
            wmma::mma_sync(c[0][0], a0, b0, c[0][0]);
            wmma::mma_sync(c[0][1], a0, b1, c[0][1]);
            wmma::mma_sync(c[1][0], a1, b0, c[1][0]);
            wmma::mma_sync(c[1][1], a1, b1, c[1][1]);
        }
        __syncthreads();
    }
#pragma unroll
    for (int i = 0; i < 2; ++i)
#pragma unroll
        for (int j = 0; j < 2; ++j)
            wmma::store_matrix_sync(&Cs[wm * 32 + i * 16][wn * 32 + j * 16], c[i][j], 64,
                                    wmma::mem_row_major);
    __syncthreads();
#pragma unroll
    for (int l = 0; l < 4; ++l) {
        int idx = tid + l * 256;
        int r = idx >> 3, seg = (idx & 7) * 8;
        int gr = bm + r;
        if (gr < M) {
            float4 v0 = *(const float4*)&Cs[r][seg];
            float4 v1 = *(const float4*)&Cs[r][seg + 4];
            uint4 ov; __half2* oh = (__half2*)&ov;
            oh[0] = __floats2half2_rn(v0.x, v0.y);
            oh[1] = __floats2half2_rn(v0.z, v0.w);
            oh[2] = __floats2half2_rn(v1.x, v1.y);
            oh[3] = __floats2half2_rn(v1.z, v1.w);
            *(uint4*)(C + (size_t)gr * 256 + bn + seg) = ov;
        }
    }
}

// ---------------- quantize hw rows to int8 (warp per row); scale only ----------------
__global__ void k_quant(const __half* __restrict__ hw) {
    int row = blockIdx.x * 8 + (threadIdx.x >> 5);
    if (row >= NUM_PROTEINS) return;
    int lane = threadIdx.x & 31;
    uint4 v = *(const uint4*)(hw + (size_t)row * EMBED + lane * 8);
    __half2* h = (__half2*)&v;
    float f[8];
#pragma unroll
    for (int q = 0; q < 4; ++q) {
        float2 p = __half22float2(h[q]);
        f[2 * q] = p.x; f[2 * q + 1] = p.y;
    }
    float m = 0.f;
#pragma unroll
    for (int i = 0; i < 8; ++i) m = fmaxf(m, fabsf(f[i]));
#pragma unroll
    for (int off = 16; off > 0; off >>= 1)
        m = fmaxf(m, __shfl_xor_sync(0xffffffffu, m, off));
    float inv = (m > 1e-30f) ? 127.f / m : 0.f;
    int b[8];
#pragma unroll
    for (int i = 0; i < 8; ++i) {
        float q = fminf(fmaxf(f[i] * inv, -127.f), 127.f);
        b[i] = __float2int_rn(q);
    }
    uint2 o;
    o.x = (unsigned)(b[0] & 255) | ((unsigned)(b[1] & 255) << 8) |
          ((unsigned)(b[2] & 255) << 16) | ((unsigned)(b[3] & 255) << 24);
    o.y = (unsigned)(b[4] & 255) | ((unsigned)(b[5] & 255) << 8) |
          ((unsigned)(b[6] & 255) << 16) | ((unsigned)(b[7] & 255) << 24);
    g_q8v[(size_t)row * 32 + lane] = o;
    if (lane == 0) g_qs[row] = m * (1.f / 127.f);
}

// ---------------- CSR aggregation: half2 magic-bias int8 gather (2-wide) ----------------
// LAYER=1: out fp16 h1 (relu). LAYER=2: +resid, quantize out to g_h2q/g_h2s.
template<int LAYER>
__global__ void k_agg8(const __half* __restrict__ hw, const float* __restrict__ bias,
                       const __half* __restrict__ resid, __half* __restrict__ outp) {
    int row = (blockIdx.x * blockDim.x + threadIdx.x) >> 5;
    if (row >= NUM_PROTEINS) return;
    int lane = threadIdx.x & 31;
    const int8_t* q8 = (const int8_t*)g_q8v;
    __half2 hacc[4];
    unsigned z = 0;
#pragma unroll
    for (int i = 0; i < 4; ++i) hacc[i] = *(__half2*)&z;
    int beg = g_rowstart[row], end = g_rowstart[row + 1];
    float dinv_d = g_dinv[row];

    for (int base = beg; base < end; base += 32) {
        int idx = base + lane;
        int      sreg = 0;
        unsigned wreg = 0;
        if (idx < end) {
            sreg = g_esrc[idx];
            wreg = packw2(g_qs[sreg] * g_dinv[sreg]);
        }
        int n = end - base; if (n > 32) n = 32;
        int j = 0;
        for (; j + 2 <= n; j += 2) {
            int      s0 = __shfl_sync(0xffffffffu, sreg, j);
            unsigned w0 = __shfl_sync(0xffffffffu, wreg, j);
            int      s1 = __shfl_sync(0xffffffffu, sreg, j + 1);
            unsigned w1 = __shfl_sync(0xffffffffu, wreg, j + 1);
            uint2 v0 = *(const uint2*)(q8 + (size_t)s0 * EMBED + lane * 8);
            uint2 v1 = *(const uint2*)(q8 + (size_t)s1 * EMBED + lane * 8);
            fma8h(hacc, w0, v0);
            fma8h(hacc, w1, v1);
        }
        if (j < n) {
            int      s0 = __shfl_sync(0xffffffffu, sreg, j);
            unsigned w0 = __shfl_sync(0xffffffffu, wreg, j);
            uint2 v0 = *(const uint2*)(q8 + (size_t)s0 * EMBED + lane * 8);
            fma8h(hacc, w0, v0);
        }
    }

    float acc[8];
#pragma unroll
    for (int q = 0; q < 4; ++q) {
        float2 f = __half22float2(hacc[q]);
        acc[2 * q] = f.x; acc[2 * q + 1] = f.y;
    }

    // self term from fp16 hw (exact path), bias, epilogue
    uint4 sv = *(const uint4*)(hw + (size_t)row * EMBED + lane * 8);
    __half2* sh = (__half2*)&sv;
    float4 b0 = *(const float4*)(bias + lane * 8);
    float4 b1 = *(const float4*)(bias + lane * 8 + 4);
    float bb[8] = {b0.x, b0.y, b0.z, b0.w, b1.x, b1.y, b1.z, b1.w};
#pragma unroll
    for (int q = 0; q < 4; ++q) {
        float2 f = __half22float2(sh[q]);
        acc[2 * q]     = (acc[2 * q]     + dinv_d * f.x) * dinv_d + bb[2 * q];
        acc[2 * q + 1] = (acc[2 * q + 1] + dinv_d * f.y) * dinv_d + bb[2 * q + 1];
    }
    if (LAYER == 1) {
#pragma unroll
        for (int i = 0; i < 8; ++i) acc[i] = fmaxf(acc[i], 0.f);
        uint4 ov; __half2* oh = (__half2*)&ov;
#pragma unroll
        for (int q = 0; q < 4; ++q) oh[q] = __floats2half2_rn(acc[2 * q], acc[2 * q + 1]);
        *(uint4*)(outp + (size_t)row * EMBED + lane * 8) = ov;
    } else {
        uint4 rv = *(const uint4*)(resid + (size_t)row * EMBED + lane * 8);
        __half2* rh = (__half2*)&rv;
#pragma unroll
        for (int q = 0; q < 4; ++q) {
            float2 f = __half22float2(rh[q]);
            acc[2 * q] += f.x; acc[2 * q + 1] += f.y;
        }
        float m = 0.f;
#pragma unroll
        for (int i = 0; i < 8; ++i) m = fmaxf(m, fabsf(acc[i]));
#pragma unroll
        for (int off = 16; off > 0; off >>= 1)
            m = fmaxf(m, __shfl_xor_sync(0xffffffffu, m, off));
        float inv = (m > 1e-30f) ? 127.f / m : 0.f;
        int b[8];
#pragma unroll
        for (int i = 0; i < 8; ++i) {
            float q = fminf(fmaxf(acc[i] * inv, -127.f), 127.f);
            b[i] = __float2int_rn(q);
        }
        uint2 o;
        o.x = (unsigned)(b[0] & 255) | ((unsigned)(b[1] & 255) << 8) |
              ((unsigned)(b[2] & 255) << 16) | ((unsigned)(b[3] & 255) << 24);
        o.y = (unsigned)(b[4] & 255) | ((unsigned)(b[5] & 255) << 8) |
              ((unsigned)(b[6] & 255) << 16) | ((unsigned)(b[7] & 255) << 24);
        g_h2q[(size_t)row * 32 + lane] = o;
        if (lane == 0) g_h2s[row] = m * (1.f / 127.f);
    }
}

// ---------------- int8 pooling: agg-style shuffle-broadcast, half2 accumulate ----------------
__global__ void k_pool8(const int* __restrict__ nodes, const int* __restrict__ sga) {
    __shared__ float sm[8][256];
    __shared__ int sbound[2];
    int d = blockIdx.x;
    int lane = threadIdx.x & 31, w = threadIdx.x >> 5;
    if (threadIdx.x < 2) {
        int target = d + threadIdx.x;
        int lo = 0, hi = N_SG;
        while (lo < hi) {
            int mid = (lo + hi) >> 1;
            if (sga[mid] < target) lo = mid + 1; else hi = mid;
        }
        sbound[threadIdx.x] = lo;
    }
    __syncthreads();
    int s = sbound[0], e = sbound[1];
    int cnt = e - s;
    int chunk = (cnt + 7) >> 3;
    int ws = s + w * chunk;
    int we = ws + chunk; if (we > e) we = e;

    const int8_t* h2 = (const int8_t*)g_h2q;
    __half2 hacc[4];
    unsigned z = 0;
#pragma unroll
    for (int i = 0; i < 4; ++i) hacc[i] = *(__half2*)&z;

    for (int base = ws; base < we; base += 32) {
        int idx = base + lane;
        int      nreg = 0;
        unsigned wreg = 0;
        if (idx < we) {
            nreg = nodes[idx];
            wreg = packw2(g_h2s[nreg]);
        }
        int n = we - base; if (n > 32) n = 32;
        int j = 0;
        for (; j + 2 <= n; j += 2) {
            int      n0 = __shfl_sync(0xffffffffu, nreg, j);
            unsigned w0 = __shfl_sync(0xffffffffu, wreg, j);
            int      n1 = __shfl_sync(0xffffffffu, nreg, j + 1);
            unsigned w1 = __shfl_sync(0xffffffffu, wreg, j + 1);
            uint2 v0 = *(const uint2*)(h2 + (size_t)n0 * EMBED + lane * 8);
            uint2 v1 = *(const uint2*)(h2 + (size_t)n1 * EMBED + lane * 8);
            fma8h(hacc, w0, v0);
            fma8h(hacc, w1, v1);
        }
        if (j < n) {
            int      n0 = __shfl_sync(0xffffffffu, nreg, j);
            unsigned w0 = __shfl_sync(0xffffffffu, wreg, j);
            uint2 v0 = *(const uint2*)(h2 + (size_t)n0 * EMBED + lane * 8);
            fma8h(hacc, w0, v0);
        }
    }
#pragma unroll
    for (int q = 0; q < 4; ++q) {
        float2 f = __half22float2(hacc[q]);
        sm[w][lane * 8 + 2 * q]     = f.x;
        sm[w][lane * 8 + 2 * q + 1] = f.y;
    }
    __syncthreads();
    int c = threadIdx.x;
    float t = sm[0][c] + sm[1][c] + sm[2][c] + sm[3][c]
            + sm[4][c] + sm[5][c] + sm[6][c] + sm[7][c];
    int cc = cnt; if (cc < 1) cc = 1;
    g_demb[(size_t)d * EMBED + c] = t * (1.0f / (float)cc);
}

// ---------------- head ----------------
__global__ void k_head(const int* __restrict__ ddb, float* __restrict__ out) {
    int warp = (blockIdx.x * blockDim.x + threadIdx.x) >> 5;
    if (warp >= B_DD) return;
    int lane = threadIdx.x & 31;
    int a = ddb[warp];
    int b = ddb[B_DD + warp];
    const float4* pa = (const float4*)(g_demb + (size_t)a * EMBED + lane * 8);
    const float4* pb = (const float4*)(g_demb + (size_t)b * EMBED + lane * 8);
    float4 a0 = pa[0], a1 = pa[1];
    float4 b0 = pb[0], b1 = pb[1];
    float dot = a0.x * b0.x + a0.y * b0.y + a0.z * b0.z + a0.w * b0.w
              + a1.x * b1.x + a1.y * b1.y + a1.z * b1.z + a1.w * b1.w;
#pragma unroll
    for (int off = 16; off > 0; off >>= 1)
        dot += __shfl_down_sync(0xffffffffu, dot, off);
    if (lane == 0) out[warp] = dot;
}

// ---------------- launch (R8 structure: fork after prep0) ----------------
extern "C" void kernel_launch(void* const* d_in, const int* in_sizes, int n_in,
                              void* d_out, int out_size) {
    const float* x   = (const float*)d_in[0];
    const int*   ddb = (const int*)  d_in[1];
    const int*   ei  = (const int*)  d_in[4];
    const int*   sgn = (const int*)  d_in[5];
    const int*   sga = (const int*)  d_in[6];
    const float* W1  = (const float*)d_in[7];
    const float* b1  = (const float*)d_in[8];
    const float* W2  = (const float*)d_in[9];
    const float* b2  = (const float*)d_in[10];
    float* out = (float*)d_out;

    __half *hwh, *h1h, *W1h, *W2h;
    cudaGetSymbolAddress((void**)&hwh, g_hwh4);
    cudaGetSymbolAddress((void**)&h1h, g_h1h4);
    cudaGetSymbolAddress((void**)&W1h, g_W1h4);
    cudaGetSymbolAddress((void**)&W2h, g_W2h4);

    static cudaStream_t s_side = nullptr;
    static cudaEvent_t  s_ev0 = nullptr, s_ev1 = nullptr;
    if (!s_side) {
        cudaStreamCreateWithFlags(&s_side, cudaStreamNonBlocking);
        cudaEventCreateWithFlags(&s_ev0, cudaEventDisableTiming);
        cudaEventCreateWithFlags(&s_ev1, cudaEventDisableTiming);
    }
    cudaStream_t s_main = 0;

    // prep0 zeroes counters and converts weights; both branches need it
    k_prep0<<<128, 256, 0, s_main>>>(W1, W2, W1h, W2h);
    cudaEventRecord(s_ev0, s_main);
    cudaStreamWaitEvent(s_side, s_ev0, 0);

    // side branch: CSR construction (count -> fused scan -> fill)
    k_count<<<(E_SG / 8 + 255) / 256, 256, 0, s_side>>>(ei + E_SG);
    k_scanall<<<NBLK, 128, 0, s_side>>>();
    k_fill<<<(E_SG + 255) / 256, 256, 0, s_side>>>(ei);
    cudaEventRecord(s_ev1, s_side);

    // main branch: GEMM1 + quant1 (independent of CSR)
    dim3 ggrid(NBLK, 256 / 64);
    k_gemm_w<0><<<ggrid, 256, 0, s_main>>>((const void*)x, W1h, hwh, NUM_PROTEINS);
    k_quant<<<(NUM_PROTEINS + 7) / 8, 256, 0, s_main>>>(hwh);

    // join: agg1 needs CSR + quant1
    cudaStreamWaitEvent(s_main, s_ev1, 0);
    k_agg8<1><<<(NUM_PROTEINS * 32 + 255) / 256, 256, 0, s_main>>>(hwh, b1, (const __half*)nullptr, h1h);
    // Layer 2 (residual) -> int8 h2
    k_gemm_w<1><<<ggrid, 256, 0, s_main>>>((const void*)h1h, W2h, hwh, NUM_PROTEINS);
    k_quant<<<(NUM_PROTEINS + 7) / 8, 256, 0, s_main>>>(hwh);
    k_agg8<2><<<(NUM_PROTEINS * 32 + 255) / 256, 256, 0, s_main>>>(hwh, b2, h1h, (__half*)nullptr);

    k_pool8<<<NUM_DRUGS, 256, 0, s_main>>>(sgn, sga);
    k_head<<<(B_DD * 32 + 255) / 256, 256, 0, s_main>>>(ddb, out);
}

// round 16
// speedup vs baseline: 1.0376x; 1.0376x over previous
#include <cuda_runtime.h>
#include <cuda_fp16.h>
#include <mma.h>
#include <cstdint>
using namespace nvcuda;

#define NUM_PROTEINS 19000
#define NUM_DRUGS    1024
#define EMBED        256
#define E_SG         1500000
#define N_SG         800000
#define B_DD         4096
#define NBLK         149            // ceil(19000/128)

// ---------------- scratch (device globals; no allocation) ----------------
__device__ uint4 g_hwh4[NUM_PROTEINS * EMBED / 8];      // GEMM out fp16
__device__ uint4 g_h1h4[NUM_PROTEINS * EMBED / 8];      // h1 fp16
__device__ uint2 g_q8v [NUM_PROTEINS * EMBED / 8];      // hw quantized int8
__device__ uint2 g_h2q [NUM_PROTEINS * EMBED / 8];      // h2 quantized int8
__device__ float g_h2s [NUM_PROTEINS];                  // h2 row scales
__device__ float g_qs  [NUM_PROTEINS];                  // quant row scale (m/127)
__device__ uint4 g_W1h4[EMBED * EMBED / 8];
__device__ uint4 g_W2h4[EMBED * EMBED / 8];
__device__ int   g_degi[NUM_PROTEINS];
__device__ float g_dinv[NUM_PROTEINS];
__device__ int   g_rowstart[NUM_PROTEINS + 1];
__device__ int   g_rank[E_SG];
__device__ int   g_esrc[E_SG];
__device__ int   g_bsum[NBLK];
__device__ int   g_boff[NBLK];
__device__ float g_demb[NUM_DRUGS * EMBED];

// half2 magic-bias int8 decode + fused multiply-accumulate (R13-proven).
__device__ __forceinline__ void fma8h(__half2* acc, unsigned wu, uint2 v) {
    __half2 w2 = *(__half2*)&wu;
    unsigned cbits = 0x64806480u;              // half2(1152, 1152)
    __half2 c2 = *(__half2*)&cbits;
    unsigned ux = v.x ^ 0x80808080u;
    unsigned uy = v.y ^ 0x80808080u;
    unsigned p0 = __byte_perm(ux, 0x64646464u, 0x4140);
    unsigned p1 = __byte_perm(ux, 0x64646464u, 0x4342);
    unsigned p2 = __byte_perm(uy, 0x64646464u, 0x4140);
    unsigned p3 = __byte_perm(uy, 0x64646464u, 0x4342);
    acc[0] = __hfma2(w2, __hsub2(*(__half2*)&p0, c2), acc[0]);
    acc[1] = __hfma2(w2, __hsub2(*(__half2*)&p1, c2), acc[1]);
    acc[2] = __hfma2(w2, __hsub2(*(__half2*)&p2, c2), acc[2]);
    acc[3] = __hfma2(w2, __hsub2(*(__half2*)&p3, c2), acc[3]);
}

// pack float weight into replicated half2 bits
__device__ __forceinline__ unsigned packw2(float w) {
    unsigned hb = (unsigned)__half_as_ushort(__float2half_rn(w));
    return hb | (hb << 16);
}

// ---------------- prep0: convert W1/W2 to fp16, zero degree counters ----------------
__global__ void k_prep0(const float* __restrict__ W1, const float* __restrict__ W2,
                        __half* __restrict__ W1h, __half* __restrict__ W2h) {
    int i = blockIdx.x * blockDim.x + threadIdx.x;
    const int n4 = EMBED * EMBED / 4;
    if (i < n4) {
        float4 v = ((const float4*)W1)[i];
        ((__half2*)W1h)[2 * i]     = __floats2half2_rn(v.x, v.y);
        ((__half2*)W1h)[2 * i + 1] = __floats2half2_rn(v.z, v.w);
    } else {
        int j = i - n4;
        float4 v = ((const float4*)W2)[j];
        ((__half2*)W2h)[2 * j]     = __floats2half2_rn(v.x, v.y);
        ((__half2*)W2h)[2 * j + 1] = __floats2half2_rn(v.z, v.w);
    }
    if (i < NUM_PROTEINS) g_degi[i] = 0;
}

// ---------------- degree count (4 edges/thread) + free rank capture ----------------
__global__ void k_count(const int* __restrict__ dstb) {
    int t = blockIdx.x * blockDim.x + threadIdx.x;
    int e4 = t * 4;
    if (e4 + 4 <= E_SG) {
        int4 d = *(const int4*)(dstb + e4);
        int4 r;
        r.x = atomicAdd(&g_degi[d.x], 1);
        r.y = atomicAdd(&g_degi[d.y], 1);
        r.z = atomicAdd(&g_degi[d.z], 1);
        r.w = atomicAdd(&g_degi[d.w], 1);
        *(int4*)(g_rank + e4) = r;
    } else {
        for (int e = e4; e < E_SG; ++e)
            g_rank[e] = atomicAdd(&g_degi[dstb[e]], 1);
    }
}

// ---------------- scan phase 1 ----------------
__global__ void k_bsum() {
    __shared__ int ws[4];
    int j = blockIdx.x * 128 + threadIdx.x;
    int v = (j < NUM_PROTEINS) ? g_degi[j] : 0;
#pragma unroll
    for (int off = 16; off > 0; off >>= 1) v += __shfl_down_sync(0xffffffffu, v, off);
    int lane = threadIdx.x & 31, w = threadIdx.x >> 5;
    if (lane == 0) ws[w] = v;
    __syncthreads();
    if (threadIdx.x == 0) g_bsum[blockIdx.x] = ws[0] + ws[1] + ws[2] + ws[3];
}

// ---------------- scan phase 2 ----------------
__global__ void k_bscan() {
    __shared__ int wsum[6];
    int t = threadIdx.x;
    int lane = t & 31, w = t >> 5;
    int s = (t < NBLK) ? g_bsum[t] : 0;
    int v = s;
#pragma unroll
    for (int off = 1; off < 32; off <<= 1) {
        int u = __shfl_up_sync(0xffffffffu, v, off);
        if (lane >= off) v += u;
    }
    if (lane == 31) wsum[w] = v;
    __syncthreads();
    if (w == 0 && lane < 6) {
        int x = wsum[lane];
#pragma unroll
        for (int off = 1; off < 6; off <<= 1) {
            int u = __shfl_up_sync(0x3fu, x, off);
            if (lane >= off) x += u;
        }
        wsum[lane] = x;
    }
    __syncthreads();
    int excl = v - s + (w ? wsum[w - 1] : 0);
    if (t < NBLK) g_boff[t] = excl;
}

// ---------------- scan phase 3: rowstart + dinv (no cursor needed) ----------------
__global__ void k_write() {
    __shared__ int wsum[4];
    int t = threadIdx.x;
    int j = blockIdx.x * 128 + t;
    int d = (j < NUM_PROTEINS) ? g_degi[j] : 0;
    int lane = t & 31, w = t >> 5;
    int v = d;
#pragma unroll
    for (int off = 1; off < 32; off <<= 1) {
        int u = __shfl_up_sync(0xffffffffu, v, off);
        if (lane >= off) v += u;
    }
    if (lane == 31) wsum[w] = v;
    __syncthreads();
    if (w == 0 && lane < 4) {
        int x = wsum[lane];
#pragma unroll
        for (int off = 1; off < 4; off <<= 1) {
            int u = __shfl_up_sync(0xfu, x, off);
            if (lane >= off) x += u;
        }
        wsum[lane] = x;
    }
    __syncthreads();
    int run = g_boff[blockIdx.x] + v - d + (w ? wsum[w - 1] : 0);
    if (j < NUM_PROTEINS) {
        g_rowstart[j] = run;
        g_dinv[j]     = rsqrtf((float)d + 1.0f);
    }
    if (j == 0) g_rowstart[NUM_PROTEINS] = E_SG;
}

// ---------------- CSR fill: atomic-free streaming (rank precomputed) ----------------
__global__ void k_fill(const int* __restrict__ ei) {
    int e = blockIdx.x * blockDim.x + threadIdx.x;
    if (e >= E_SG) return;
    int s = ei[e];
    int d = ei[E_SG + e];
    int r = g_rank[e];
    g_esrc[g_rowstart[d] + r] = s;
}

// ---------------- WMMA fp16 GEMM ----------------
template<int AHALF>
__global__ void k_gemm_w(const void* __restrict__ Ap, const __half* __restrict__ B,
                         __half* __restrict__ C, int M) {
    __shared__ __align__(16) __half As[128][40];
    __shared__ __align__(16) __half Bs[32][72];
    __shared__ __align__(16) float  Cs[128][64];
    int bm = blockIdx.x * 128, bn = blockIdx.y * 64;
    int tid = threadIdx.x;
    int warp = tid >> 5;
    int wm = warp & 3, wn = warp >> 2;
    wmma::fragment<wmma::accumulator, 16, 16, 16, float> c[2][2];
#pragma unroll
    for (int i = 0; i < 2; ++i)
#pragma unroll
        for (int j = 0; j < 2; ++j) wmma::fill_fragment(c[i][j], 0.f);

    for (int k0 = 0; k0 < 256; k0 += 32) {
        if (AHALF) {
            const __half* A = (const __half*)Ap;
#pragma unroll
            for (int l = 0; l < 2; ++l) {
                int idx = tid + l * 256;
                int r = idx >> 2, seg = (idx & 3) * 8;
                uint4 v = make_uint4(0, 0, 0, 0);
                int gr = bm + r;
                if (gr < M) v = *(const uint4*)(A + (size_t)gr * 256 + k0 + seg);
                *(uint4*)&As[r][seg] = v;
            }
        } else {
            const float* A = (const float*)Ap;
#pragma unroll
            for (int l = 0; l < 4; ++l) {
                int idx = tid + l * 256;
                int r = idx >> 3, c4 = (idx & 7) * 4;
                float4 v = make_float4(0.f, 0.f, 0.f, 0.f);
                int gr = bm + r;
                if (gr < M) v = *(const float4*)(A + (size_t)gr * 256 + k0 + c4);
                *(__half2*)&As[r][c4]     = __floats2half2_rn(v.x, v.y);
                *(__half2*)&As[r][c4 + 2] = __floats2half2_rn(v.z, v.w);
            }
        }
        {
            int r = tid >> 3, seg = (tid & 7) * 8;
            uint4 v = *(const uint4*)(B + (size_t)(k0 + r) * 256 + bn + seg);
            *(uint4*)&Bs[r][seg] = v;
        }
        __syncthreads();
#pragma unroll
        for (int kk = 0; kk < 32; kk += 16) {
            wmma::fragment<wmma::matrix_a, 16, 16, 16, __half, wmma::row_major> a0, a1;
            wmma::fragment<wmma::matrix_b, 16, 16, 16, __half, wmma::row_major> b0, b1;
            wmma::load_matrix_sync(a0, &As[wm * 32][kk], 40);
            wmma::load_matrix_sync(a1, &As[wm * 32 + 16][kk], 40);
            wmma::load_matrix_sync(b0, &Bs[kk][wn * 32], 72);
            wmma::load_matrix_sync(b1, &Bs[kk][wn * 32 + 16], 72);
            wmma::mma_sync(c[0][0], a0, b0, c[0][0]);
            wmma::mma_sync(c[0][1], a0, b1, c[0][1]);
            wmma::mma_sync(c[1][0], a1, b0, c[1][0]);
            wmma::mma_sync(c[1][1], a1, b1, c[1][1]);
        }
        __syncthreads();
    }
#pragma unroll
    for (int i = 0; i < 2; ++i)
#pragma unroll
        for (int j = 0; j < 2; ++j)
            wmma::store_matrix_sync(&Cs[wm * 32 + i * 16][wn * 32 + j * 16], c[i][j], 64,
                                    wmma::mem_row_major);
    __syncthreads();
#pragma unroll
    for (int l = 0; l < 4; ++l) {
        int idx = tid + l * 256;
        int r = idx >> 3, seg = (idx & 7) * 8;
        int gr = bm + r;
        if (gr < M) {
            float4 v0 = *(const float4*)&Cs[r][seg];
            float4 v1 = *(const float4*)&Cs[r][seg + 4];
            uint4 ov; __half2* oh = (__half2*)&ov;
            oh[0] = __floats2half2_rn(v0.x, v0.y);
            oh[1] = __floats2half2_rn(v0.z, v0.w);
            oh[2] = __floats2half2_rn(v1.x, v1.y);
            oh[3] = __floats2half2_rn(v1.z, v1.w);
            *(uint4*)(C + (size_t)gr * 256 + bn + seg) = ov;
        }
    }
}

// ---------------- quantize hw rows to int8 (warp per row); scale only ----------------
__global__ void k_quant(const __half* __restrict__ hw) {
    int row = blockIdx.x * 8 + (threadIdx.x >> 5);
    if (row >= NUM_PROTEINS) return;
    int lane = threadIdx.x & 31;
    uint4 v = *(const uint4*)(hw + (size_t)row * EMBED + lane * 8);
    __half2* h = (__half2*)&v;
    float f[8];
#pragma unroll
    for (int q = 0; q < 4; ++q) {
        float2 p = __half22float2(h[q]);
        f[2 * q] = p.x; f[2 * q + 1] = p.y;
    }
    float m = 0.f;
#pragma unroll
    for (int i = 0; i < 8; ++i) m = fmaxf(m, fabsf(f[i]));
#pragma unroll
    for (int off = 16; off > 0; off >>= 1)
        m = fmaxf(m, __shfl_xor_sync(0xffffffffu, m, off));
    float inv = (m > 1e-30f) ? 127.f / m : 0.f;
    int b[8];
#pragma unroll
    for (int i = 0; i < 8; ++i) {
        float q = fminf(fmaxf(f[i] * inv, -127.f), 127.f);
        b[i] = __float2int_rn(q);
    }
    uint2 o;
    o.x = (unsigned)(b[0] & 255) | ((unsigned)(b[1] & 255) << 8) |
          ((unsigned)(b[2] & 255) << 16) | ((unsigned)(b[3] & 255) << 24);
    o.y = (unsigned)(b[4] & 255) | ((unsigned)(b[5] & 255) << 8) |
          ((unsigned)(b[6] & 255) << 16) | ((unsigned)(b[7] & 255) << 24);
    g_q8v[(size_t)row * 32 + lane] = o;
    if (lane == 0) g_qs[row] = m * (1.f / 127.f);
}

// ---------------- CSR aggregation: half2 magic-bias int8 gather (2-wide) ----------------
// LAYER=1: out fp16 h1 (relu). LAYER=2: +resid, quantize out to g_h2q/g_h2s.
template<int LAYER>
__global__ void k_agg8(const __half* __restrict__ hw, const float* __restrict__ bias,
                       const __half* __restrict__ resid, __half* __restrict__ outp) {
    int row = (blockIdx.x * blockDim.x + threadIdx.x) >> 5;
    if (row >= NUM_PROTEINS) return;
    int lane = threadIdx.x & 31;
    const int8_t* q8 = (const int8_t*)g_q8v;
    __half2 hacc[4];
    unsigned z = 0;
#pragma unroll
    for (int i = 0; i < 4; ++i) hacc[i] = *(__half2*)&z;
    int beg = g_rowstart[row], end = g_rowstart[row + 1];
    float dinv_d = g_dinv[row];

    for (int base = beg; base < end; base += 32) {
        int idx = base + lane;
        int      sreg = 0;
        unsigned wreg = 0;
        if (idx < end) {
            sreg = g_esrc[idx];
            wreg = packw2(g_qs[sreg] * g_dinv[sreg]);
        }
        int n = end - base; if (n > 32) n = 32;
        int j = 0;
        for (; j + 2 <= n; j += 2) {
            int      s0 = __shfl_sync(0xffffffffu, sreg, j);
            unsigned w0 = __shfl_sync(0xffffffffu, wreg, j);
            int      s1 = __shfl_sync(0xffffffffu, sreg, j + 1);
            unsigned w1 = __shfl_sync(0xffffffffu, wreg, j + 1);
            uint2 v0 = *(const uint2*)(q8 + (size_t)s0 * EMBED + lane * 8);
            uint2 v1 = *(const uint2*)(q8 + (size_t)s1 * EMBED + lane * 8);
            fma8h(hacc, w0, v0);
            fma8h(hacc, w1, v1);
        }
        if (j < n) {
            int      s0 = __shfl_sync(0xffffffffu, sreg, j);
            unsigned w0 = __shfl_sync(0xffffffffu, wreg, j);
            uint2 v0 = *(const uint2*)(q8 + (size_t)s0 * EMBED + lane * 8);
            fma8h(hacc, w0, v0);
        }
    }

    float acc[8];
#pragma unroll
    for (int q = 0; q < 4; ++q) {
        float2 f = __half22float2(hacc[q]);
        acc[2 * q] = f.x; acc[2 * q + 1] = f.y;
    }

    // self term from fp16 hw (exact path), bias, epilogue
    uint4 sv = *(const uint4*)(hw + (size_t)row * EMBED + lane * 8);
    __half2* sh = (__half2*)&sv;
    float4 b0 = *(const float4*)(bias + lane * 8);
    float4 b1 = *(const float4*)(bias + lane * 8 + 4);
    float bb[8] = {b0.x, b0.y, b0.z, b0.w, b1.x, b1.y, b1.z, b1.w};
#pragma unroll
    for (int q = 0; q < 4; ++q) {
        float2 f = __half22float2(sh[q]);
        acc[2 * q]     = (acc[2 * q]     + dinv_d * f.x) * dinv_d + bb[2 * q];
        acc[2 * q + 1] = (acc[2 * q + 1] + dinv_d * f.y) * dinv_d + bb[2 * q + 1];
    }
    if (LAYER == 1) {
#pragma unroll
        for (int i = 0; i < 8; ++i) acc[i] = fmaxf(acc[i], 0.f);
        uint4 ov; __half2* oh = (__half2*)&ov;
#pragma unroll
        for (int q = 0; q < 4; ++q) oh[q] = __floats2half2_rn(acc[2 * q], acc[2 * q + 1]);
        *(uint4*)(outp + (size_t)row * EMBED + lane * 8) = ov;
    } else {
        uint4 rv = *(const uint4*)(resid + (size_t)row * EMBED + lane * 8);
        __half2* rh = (__half2*)&rv;
#pragma unroll
        for (int q = 0; q < 4; ++q) {
            float2 f = __half22float2(rh[q]);
            acc[2 * q] += f.x; acc[2 * q + 1] += f.y;
        }
        float m = 0.f;
#pragma unroll
        for (int i = 0; i < 8; ++i) m = fmaxf(m, fabsf(acc[i]));
#pragma unroll
        for (int off = 16; off > 0; off >>= 1)
            m = fmaxf(m, __shfl_xor_sync(0xffffffffu, m, off));
        float inv = (m > 1e-30f) ? 127.f / m : 0.f;
        int b[8];
#pragma unroll
        for (int i = 0; i < 8; ++i) {
            float q = fminf(fmaxf(acc[i] * inv, -127.f), 127.f);
            b[i] = __float2int_rn(q);
        }
        uint2 o;
        o.x = (unsigned)(b[0] & 255) | ((unsigned)(b[1] & 255) << 8) |
              ((unsigned)(b[2] & 255) << 16) | ((unsigned)(b[3] & 255) << 24);
        o.y = (unsigned)(b[4] & 255) | ((unsigned)(b[5] & 255) << 8) |
              ((unsigned)(b[6] & 255) << 16) | ((unsigned)(b[7] & 255) << 24);
        g_h2q[(size_t)row * 32 + lane] = o;
        if (lane == 0) g_h2s[row] = m * (1.f / 127.f);
    }
}

// ---------------- int8 pooling: agg-style shuffle-broadcast, half2 accumulate ----------------
__global__ void k_pool8(const int* __restrict__ nodes, const int* __restrict__ sga) {
    __shared__ float sm[8][256];
    __shared__ int sbound[2];
    int d = blockIdx.x;
    int lane = threadIdx.x & 31, w = threadIdx.x >> 5;
    if (threadIdx.x < 2) {
        int target = d + threadIdx.x;
        int lo = 0, hi = N_SG;
        while (lo < hi) {
            int mid = (lo + hi) >> 1;
            if (sga[mid] < target) lo = mid + 1; else hi = mid;
        }
        sbound[threadIdx.x] = lo;
    }
    __syncthreads();
    int s = sbound[0], e = sbound[1];
    int cnt = e - s;
    int chunk = (cnt + 7) >> 3;
    int ws = s + w * chunk;
    int we = ws + chunk; if (we > e) we = e;

    const int8_t* h2 = (const int8_t*)g_h2q;
    __half2 hacc[4];
    unsigned z = 0;
#pragma unroll
    for (int i = 0; i < 4; ++i) hacc[i] = *(__half2*)&z;

    for (int base = ws; base < we; base += 32) {
        int idx = base + lane;
        int      nreg = 0;
        unsigned wreg = 0;
        if (idx < we) {
            nreg = nodes[idx];
            wreg = packw2(g_h2s[nreg]);
        }
        int n = we - base; if (n > 32) n = 32;
        int j = 0;
        for (; j + 2 <= n; j += 2) {
            int      n0 = __shfl_sync(0xffffffffu, nreg, j);
            unsigned w0 = __shfl_sync(0xffffffffu, wreg, j);
            int      n1 = __shfl_sync(0xffffffffu, nreg, j + 1);
            unsigned w1 = __shfl_sync(0xffffffffu, wreg, j + 1);
            uint2 v0 = *(const uint2*)(h2 + (size_t)n0 * EMBED + lane * 8);
            uint2 v1 = *(const uint2*)(h2 + (size_t)n1 * EMBED + lane * 8);
            fma8h(hacc, w0, v0);
            fma8h(hacc, w1, v1);
        }
        if (j < n) {
            int      n0 = __shfl_sync(0xffffffffu, nreg, j);
            unsigned w0 = __shfl_sync(0xffffffffu, wreg, j);
            uint2 v0 = *(const uint2*)(h2 + (size_t)n0 * EMBED + lane * 8);
            fma8h(hacc, w0, v0);
        }
    }
#pragma unroll
    for (int q = 0; q < 4; ++q) {
        float2 f = __half22float2(hacc[q]);
        sm[w][lane * 8 + 2 * q]     = f.x;
        sm[w][lane * 8 + 2 * q + 1] = f.y;
    }
    __syncthreads();
    int c = threadIdx.x;
    float t = sm[0][c] + sm[1][c] + sm[2][c] + sm[3][c]
            + sm[4][c] + sm[5][c] + sm[6][c] + sm[7][c];
    int cc = cnt; if (cc < 1) cc = 1;
    g_demb[(size_t)d * EMBED + c] = t * (1.0f / (float)cc);
}

// ---------------- head ----------------
__global__ void k_head(const int* __restrict__ ddb, float* __restrict__ out) {
    int warp = (blockIdx.x * blockDim.x + threadIdx.x) >> 5;
    if (warp >= B_DD) return;
    int lane = threadIdx.x & 31;
    int a = ddb[warp];
    int b = ddb[B_DD + warp];
    const float4* pa = (const float4*)(g_demb + (size_t)a * EMBED + lane * 8);
    const float4* pb = (const float4*)(g_demb + (size_t)b * EMBED + lane * 8);
    float4 a0 = pa[0], a1 = pa[1];
    float4 b0 = pb[0], b1 = pb[1];
    float dot = a0.x * b0.x + a0.y * b0.y + a0.z * b0.z + a0.w * b0.w
              + a1.x * b1.x + a1.y * b1.y + a1.z * b1.z + a1.w * b1.w;
#pragma unroll
    for (int off = 16; off > 0; off >>= 1)
        dot += __shfl_down_sync(0xffffffffu, dot, off);
    if (lane == 0) out[warp] = dot;
}

// ---------------- launch (R14 structure: fork after prep0) ----------------
extern "C" void kernel_launch(void* const* d_in, const int* in_sizes, int n_in,
                              void* d_out, int out_size) {
    const float* x   = (const float*)d_in[0];
    const int*   ddb = (const int*)  d_in[1];
    const int*   ei  = (const int*)  d_in[4];
    const int*   sgn = (const int*)  d_in[5];
    const int*   sga = (const int*)  d_in[6];
    const float* W1  = (const float*)d_in[7];
    const float* b1  = (const float*)d_in[8];
    const float* W2  = (const float*)d_in[9];
    const float* b2  = (const float*)d_in[10];
    float* out = (float*)d_out;

    __half *hwh, *h1h, *W1h, *W2h;
    cudaGetSymbolAddress((void**)&hwh, g_hwh4);
    cudaGetSymbolAddress((void**)&h1h, g_h1h4);
    cudaGetSymbolAddress((void**)&W1h, g_W1h4);
    cudaGetSymbolAddress((void**)&W2h, g_W2h4);

    static cudaStream_t s_side = nullptr;
    static cudaEvent_t  s_ev0 = nullptr, s_ev1 = nullptr;
    if (!s_side) {
        cudaStreamCreateWithFlags(&s_side, cudaStreamNonBlocking);
        cudaEventCreateWithFlags(&s_ev0, cudaEventDisableTiming);
        cudaEventCreateWithFlags(&s_ev1, cudaEventDisableTiming);
    }
    cudaStream_t s_main = 0;

    // prep0 zeroes degree counters and converts weights; both branches need it
    k_prep0<<<128, 256, 0, s_main>>>(W1, W2, W1h, W2h);
    cudaEventRecord(s_ev0, s_main);
    cudaStreamWaitEvent(s_side, s_ev0, 0);

    // side branch: CSR construction (count+rank -> scan -> atomic-free fill)
    k_count<<<(E_SG / 4 + 255) / 256, 256, 0, s_side>>>(ei + E_SG);
    k_bsum<<<NBLK, 128, 0, s_side>>>();
    k_bscan<<<1, 192, 0, s_side>>>();
    k_write<<<NBLK, 128, 0, s_side>>>();
    k_fill<<<(E_SG + 255) / 256, 256, 0, s_side>>>(ei);
    cudaEventRecord(s_ev1, s_side);

    // main branch: GEMM1 + quant1 (independent of CSR)
    dim3 ggrid(NBLK, 256 / 64);
    k_gemm_w<0><<<ggrid, 256, 0, s_main>>>((const void*)x, W1h, hwh, NUM_PROTEINS);
    k_quant<<<(NUM_PROTEINS + 7) / 8, 256, 0, s_main>>>(hwh);

    // join: agg1 needs CSR + quant1
    cudaStreamWaitEvent(s_main, s_ev1, 0);
    k_agg8<1><<<(NUM_PROTEINS * 32 + 255) / 256, 256, 0, s_main>>>(hwh, b1, (const __half*)nullptr, h1h);
    // Layer 2 (residual) -> int8 h2
    k_gemm_w<1><<<ggrid, 256, 0, s_main>>>((const void*)h1h, W2h, hwh, NUM_PROTEINS);
    k_quant<<<(NUM_PROTEINS + 7) / 8, 256, 0, s_main>>>(hwh);
    k_agg8<2><<<(NUM_PROTEINS * 32 + 255) / 256, 256, 0, s_main>>>(hwh, b2, h1h, (__half*)nullptr);

    k_pool8<<<NUM_DRUGS, 256, 0, s_main>>>(sgn, sga);
    k_head<<<(B_DD * 32 + 255) / 256, 256, 0, s_main>>>(ddb, out);
}